// round 14
// baseline (speedup 1.0000x reference)
#include <cuda_runtime.h>
#include <cuda_bf16.h>
#include <cuda_fp16.h>
#include <math.h>
#include <stdint.h>

constexpr int BATCH = 128, SEQT = 24, EMB = 512, HID = 1024, VOC = 12000;
constexpr int MALL = SEQT * BATCH;     // 3072, row m = t*128 + b
constexpr int G4 = 4 * HID;            // 4096
constexpr int VOCP = 12032;            // VOC padded to 128
constexpr int BK = 32;                 // K chunk
constexpr int LDT = 40;                // padded smem row stride (16-bit elems)
constexpr int STAGES = 3;
constexpr uint32_t SMEMSZ_128 = STAGES * (128 + 128) * LDT * 2;  // 61440 B
constexpr uint32_t SMEMSZ_REC = STAGES * (64 + 32) * LDT * 2;    // 23040 B

// ---------------- device scratch (allocation forbidden) ---------------------
__device__ __half g_xf[(size_t)MALL * EMB];
__device__ __half g_wihf[(size_t)G4 * EMB];
__device__ __half g_whhf[(size_t)G4 * HID];   // gate-interleaved rows
__device__ __half g_wfcf[(size_t)VOCP * HID];
__device__ __half g_hf16[(size_t)MALL * HID];
__device__ float g_gpre[(size_t)MALL * G4];
__device__ float g_cbuf[2 * BATCH * HID];

// ---------------- helpers ----------------------------------------------------
__device__ __forceinline__ uint32_t smem_u32(const void* p) {
    uint32_t a;
    asm("{ .reg .u64 t; cvta.to.shared.u64 t, %1; cvt.u32.u64 %0, t; }" : "=r"(a) : "l"(p));
    return a;
}
__device__ __forceinline__ void cp16(uint32_t d, const void* s) {
    asm volatile("cp.async.cg.shared.global [%0], [%1], 16;" :: "r"(d), "l"(s));
}
__device__ __forceinline__ void cp_commit() { asm volatile("cp.async.commit_group;"); }
template <int N> __device__ __forceinline__ void cp_wait() {
    asm volatile("cp.async.wait_group %0;" :: "n"(N));
}
__device__ __forceinline__ void ldsm4(uint32_t* r, uint32_t a) {
    asm volatile("ldmatrix.sync.aligned.m8n8.x4.shared.b16 {%0,%1,%2,%3}, [%4];"
                 : "=r"(r[0]), "=r"(r[1]), "=r"(r[2]), "=r"(r[3]) : "r"(a));
}
__device__ __forceinline__ void mma16816h(float* d, const uint32_t* a, const uint32_t* b) {
    asm volatile("mma.sync.aligned.m16n8k16.row.col.f32.f16.f16.f32 "
                 "{%0,%1,%2,%3}, {%4,%5,%6,%7}, {%8,%9}, {%0,%1,%2,%3};"
                 : "+f"(d[0]), "+f"(d[1]), "+f"(d[2]), "+f"(d[3])
                 : "r"(a[0]), "r"(a[1]), "r"(a[2]), "r"(a[3]), "r"(b[0]), "r"(b[1]));
}
__device__ __forceinline__ uint2 f16x4(float4 v) {
    __half2 a = __floats2half2_rn(v.x, v.y);
    __half2 b = __floats2half2_rn(v.z, v.w);
    return make_uint2(*reinterpret_cast<uint32_t*>(&a), *reinterpret_cast<uint32_t*>(&b));
}

// ---------------- preprocessing ----------------------------------------------
// Merged convert: Wih plain | Whh interleave | Wfc padded.
// Whh interleave: dst row d -> nblk=d>>5, gate=(d>>3)&3, j=d&7 ;
// src row = gate*HID + nblk*8 + j
constexpr int S1 = G4 * EMB / 4;       // 524288
constexpr int S2 = G4 * HID / 4;       // 1048576
constexpr int S3 = VOCP * HID / 4;     // 3080192
__global__ void cvt_all(const float* __restrict__ Wih, const float* __restrict__ Whh,
                        const float* __restrict__ Wfc) {
    constexpr int TOTAL = S1 + S2 + S3;
    for (int i = blockIdx.x * blockDim.x + threadIdx.x; i < TOTAL;
         i += gridDim.x * blockDim.x) {
        if (i < S1) {
            reinterpret_cast<uint2*>(g_wihf)[i] =
                f16x4(reinterpret_cast<const float4*>(Wih)[i]);
        } else if (i < S1 + S2) {
            const int j = i - S1;
            const int d = j >> 8, k4 = j & 255;
            const int src = ((d >> 3) & 3) * HID + (d >> 5) * 8 + (d & 7);
            reinterpret_cast<uint2*>(g_whhf)[j] =
                f16x4(*reinterpret_cast<const float4*>(Whh + (size_t)src * HID + k4 * 4));
        } else {
            const int j = i - S1 - S2;
            const int r = j >> 8;
            float4 v = (r < VOC) ? reinterpret_cast<const float4*>(Wfc)[j]
                                 : make_float4(0.f, 0.f, 0.f, 0.f);
            reinterpret_cast<uint2*>(g_wfcf)[j] = f16x4(v);
        }
    }
}
__global__ void gather_f16(const float* __restrict__ enc, const int* __restrict__ caps,
                           const float* __restrict__ emb) {
    const int m = blockIdx.x, t = m >> 7, b = m & 127;
    const float* src = (t == 0) ? enc + (size_t)b * EMB
                                : emb + (size_t)caps[b * SEQT + (t - 1)] * EMB;
    const float4 v = reinterpret_cast<const float4*>(src)[threadIdx.x];
    reinterpret_cast<uint2*>(g_xf)[m * (EMB / 4) + threadIdx.x] = f16x4(v);
}

// ---------------- fp16 single-term mainloop ----------------------------------
// acc += A[MTxK] @ B[NTxK]^T. 256 threads, 8 warps.
// MT=128,NT=128: 2Mx4N (wt 64x32, MI=4,NI=4).
// MT=64, NT=32 : 4Mx2N (wt 16x16, MI=1,NI=2).
template <int MT, int NT, int MI, int NI>
__device__ __forceinline__ void gemm_main_h(
    const __half* __restrict__ A, const __half* __restrict__ B,
    int m0, int n0, int K, uint32_t sm, float (&acc)[MI][NI][4]) {
    constexpr int TAe = MT * LDT;
    constexpr int TBe = NT * LDT;
    constexpr int STAGE = TAe + TBe;
    constexpr int TOT = (MT + NT) * 4;

    const int tid = threadIdx.x, warp = tid >> 5, lane = tid & 31;
    const int wm = (MT == 128) ? (warp & 1) * 64 : (warp & 3) * 16;
    const int wn = (MT == 128) ? (warp >> 1) * 32 : (warp >> 2) * 16;
    const int l8 = lane & 7, lt = lane >> 3;
    const int nk = K / BK;

    auto load_stage = [&](int stage, int k0) {
        const uint32_t sbase = sm + stage * STAGE * 2;
#pragma unroll
        for (int idx = tid; idx < TOT; idx += 256) {
            uint32_t dst;
            const __half* src;
            if (idx < MT * 4) {
                const int r = idx >> 2, c = idx & 3;
                dst = sbase + (r * LDT + c * 8) * 2;
                src = A + (size_t)(m0 + r) * K + k0 + c * 8;
            } else {
                const int j = idx - MT * 4, r = j >> 2, c = j & 3;
                dst = sbase + (TAe + r * LDT + c * 8) * 2;
                src = B + (size_t)(n0 + r) * K + k0 + c * 8;
            }
            cp16(dst, src);
        }
        cp_commit();
    };

    load_stage(0, 0);
    load_stage(1, BK);

    for (int kc = 0; kc < nk; kc++) {
        if (kc == nk - 1) cp_wait<0>(); else cp_wait<1>();
        __syncthreads();
        if (kc + STAGES - 1 < nk)
            load_stage((kc + STAGES - 1) % STAGES, (kc + STAGES - 1) * BK);
        const uint32_t sb = sm + (kc % STAGES) * STAGE * 2;
#pragma unroll
        for (int h = 0; h < 2; h++) {
            const int kk = h * 16;
            uint32_t af[MI][4], bf[NI][2];
#pragma unroll
            for (int mi = 0; mi < MI; mi++) {
                const uint32_t ra = sb +
                    ((wm + mi * 16 + l8 + (lt & 1) * 8) * LDT + kk + (lt >> 1) * 8) * 2;
                ldsm4(af[mi], ra);
            }
#pragma unroll
            for (int nj = 0; nj < NI / 2; nj++) {
                const uint32_t rb = sb + TAe * 2 +
                    ((wn + nj * 16 + l8 + (lt >> 1) * 8) * LDT + kk + (lt & 1) * 8) * 2;
                uint32_t t4[4];
                ldsm4(t4, rb);
                bf[nj * 2][0] = t4[0]; bf[nj * 2][1] = t4[1];
                bf[nj * 2 + 1][0] = t4[2]; bf[nj * 2 + 1][1] = t4[3];
            }
#pragma unroll
            for (int mi = 0; mi < MI; mi++)
#pragma unroll
                for (int ni = 0; ni < NI; ni++)
                    mma16816h(acc[mi][ni], af[mi], bf[ni]);
        }
    }
    __syncthreads();
}

// ---------------- input-proj GEMM: C = X @ Wih^T + b_ih + b_hh ---------------
__global__ __launch_bounds__(256, 2)
void ip_gemm(const __half* __restrict__ A, const __half* __restrict__ B,
             const float* __restrict__ b1, const float* __restrict__ b2,
             float* __restrict__ C, int K, int N) {
    extern __shared__ char smraw[];
    float acc[4][4][4];
#pragma unroll
    for (int a = 0; a < 4; a++)
#pragma unroll
        for (int b = 0; b < 4; b++)
#pragma unroll
            for (int c = 0; c < 4; c++) acc[a][b][c] = 0.f;

    const int m0 = blockIdx.y * 128, n0 = blockIdx.x * 128;
    gemm_main_h<128, 128, 4, 4>(A, B, m0, n0, K, smem_u32(smraw), acc);

    const int lane = threadIdx.x & 31, warp = threadIdx.x >> 5;
    const int wm = (warp & 1) * 64, wn = (warp >> 1) * 32;
    const int g = lane >> 2, tg = lane & 3;
#pragma unroll
    for (int mi = 0; mi < 4; mi++)
#pragma unroll
        for (int half = 0; half < 2; half++) {
            const int m = m0 + wm + mi * 16 + g + half * 8;
            const size_t rowBase = (size_t)m * N;
#pragma unroll
            for (int ni = 0; ni < 4; ni++) {
                const int n = n0 + wn + ni * 8 + tg * 2;
                const float2 bb = *reinterpret_cast<const float2*>(b1 + n);
                const float2 b2v = *reinterpret_cast<const float2*>(b2 + n);
                float2 v;
                v.x = acc[mi][ni][half * 2 + 0] + bb.x + b2v.x;
                v.y = acc[mi][ni][half * 2 + 1] + bb.y + b2v.y;
                *reinterpret_cast<float2*>(C + rowBase + n) = v;
            }
        }
}

// ---------------- FC GEMM slice: one timestep row-block ----------------------
// C[(b*24+t), n] = sum_k h[m,k] * Wfc[n,k] + b_fc[n], m = mbase + local
__global__ __launch_bounds__(256, 2)
void fc_gemm(const __half* __restrict__ A, const __half* __restrict__ B,
             const float* __restrict__ b1, float* __restrict__ C, int K, int N,
             int mbase) {
    extern __shared__ char smraw[];
    float acc[4][4][4];
#pragma unroll
    for (int a = 0; a < 4; a++)
#pragma unroll
        for (int b = 0; b < 4; b++)
#pragma unroll
            for (int c = 0; c < 4; c++) acc[a][b][c] = 0.f;

    const int m0 = mbase + blockIdx.y * 128, n0 = blockIdx.x * 128;
    gemm_main_h<128, 128, 4, 4>(A, B, m0, n0, K, smem_u32(smraw), acc);

    const int lane = threadIdx.x & 31, warp = threadIdx.x >> 5;
    const int wm = (warp & 1) * 64, wn = (warp >> 1) * 32;
    const int g = lane >> 2, tg = lane & 3;
#pragma unroll
    for (int mi = 0; mi < 4; mi++)
#pragma unroll
        for (int half = 0; half < 2; half++) {
            const int m = m0 + wm + mi * 16 + g + half * 8;
            const size_t rowBase = ((size_t)(m & 127) * SEQT + (size_t)(m >> 7)) * N;
#pragma unroll
            for (int ni = 0; ni < 4; ni++) {
                const int n = n0 + wn + ni * 8 + tg * 2;
                if (n >= N) continue;
                const float2 bb = *reinterpret_cast<const float2*>(b1 + n);
                float2 v;
                v.x = acc[mi][ni][half * 2 + 0] + bb.x;
                v.y = acc[mi][ni][half * 2 + 1] + bb.y;
                *reinterpret_cast<float2*>(C + rowBase + n) = v;
            }
        }
}

// ---------------- recurrent step: 256 CTAs, tile [64 x 32], fused cell -------
// CTA: nblk = blockIdx>>1 owns hidden [nblk*8, nblk*8+8) x 4 gates (D col
// c = gate*8 + j); mh = blockIdx&1 owns batch rows [mh*64, mh*64+64).
__global__ __launch_bounds__(256, 2)
void lstm_mma_step(int t) {
    extern __shared__ char smraw[];
    const int tid = threadIdx.x;
    const int nblk = blockIdx.x >> 1;
    const int mh = blockIdx.x & 1;
    float* Cs = reinterpret_cast<float*>(smraw);   // [64][36], reuses GEMM smem

    if (t > 0) {
        float acc[1][2][4] = {};
        gemm_main_h<64, 32, 1, 2>(
            g_hf16 + (size_t)(t - 1) * BATCH * HID + (size_t)mh * 64 * HID,
            g_whhf, 0, nblk * 32, HID, smem_u32(smraw), acc);
        const int lane = tid & 31, warp = tid >> 5;
        const int wm = (warp & 3) * 16, wn = (warp >> 2) * 16;
        const int g = lane >> 2, tg = lane & 3;
#pragma unroll
        for (int half = 0; half < 2; half++) {
            const int r = wm + g + half * 8;
#pragma unroll
            for (int ni = 0; ni < 2; ni++) {
                const int c = wn + ni * 8 + tg * 2;
                float2 v;
                v.x = acc[0][ni][half * 2 + 0];
                v.y = acc[0][ni][half * 2 + 1];
                *reinterpret_cast<float2*>(&Cs[r * 36 + c]) = v;
            }
        }
        __syncthreads();
    }

    // cell update: 4 threads per batch row, 2 hidden units each
    const int bl = tid >> 2;              // local row 0..63
    const int b = mh * 64 + bl;
    const int u0 = (tid & 3) * 2;         // unit offset 0,2,4,6
    const int j0 = nblk * 8;
    const float* gp   = g_gpre + ((size_t)t * BATCH + b) * G4;
    const float* cold = g_cbuf + (size_t)(t & 1) * BATCH * HID + (size_t)b * HID;
    float*       cnew = g_cbuf + (size_t)((t + 1) & 1) * BATCH * HID + (size_t)b * HID;
    __half*      hf   = g_hf16 + ((size_t)t * BATCH + b) * HID;

    const float2 pi = *reinterpret_cast<const float2*>(gp + 0 * HID + j0 + u0);
    const float2 pf = *reinterpret_cast<const float2*>(gp + 1 * HID + j0 + u0);
    const float2 pg = *reinterpret_cast<const float2*>(gp + 2 * HID + j0 + u0);
    const float2 po = *reinterpret_cast<const float2*>(gp + 3 * HID + j0 + u0);
    float2 co = make_float2(0.f, 0.f);
    if (t > 0) co = *reinterpret_cast<const float2*>(cold + j0 + u0);

    float cn[2], hn[2];
#pragma unroll
    for (int q = 0; q < 2; q++) {
        float ai = 0.f, af = 0.f, ag = 0.f, ao = 0.f;
        if (t > 0) {
            ai = Cs[bl * 36 + 0  + u0 + q];
            af = Cs[bl * 36 + 8  + u0 + q];
            ag = Cs[bl * 36 + 16 + u0 + q];
            ao = Cs[bl * 36 + 24 + u0 + q];
        }
        const float* pip = &pi.x; const float* pfp = &pf.x;
        const float* pgp = &pg.x; const float* pop = &po.x;
        const float* cop = &co.x;
        const float gi = 1.f / (1.f + expf(-(ai + pip[q])));
        const float gf = 1.f / (1.f + expf(-(af + pfp[q])));
        const float gg = tanhf(ag + pgp[q]);
        const float go = 1.f / (1.f + expf(-(ao + pop[q])));
        const float cv = gf * cop[q] + gi * gg;
        cn[q] = cv;
        hn[q] = go * tanhf(cv);
    }
    *reinterpret_cast<float2*>(cnew + j0 + u0) = make_float2(cn[0], cn[1]);
    __half2 hp = __floats2half2_rn(hn[0], hn[1]);
    *reinterpret_cast<uint32_t*>(hf + j0 + u0) = *reinterpret_cast<uint32_t*>(&hp);
}

// ---------------- stream/event aux (created once, outside capture) -----------
struct Aux {
    cudaStream_t s2;
    cudaEvent_t ev[SEQT];
    cudaEvent_t join;
    Aux() {
        cudaStreamCreateWithFlags(&s2, cudaStreamNonBlocking);
        for (int i = 0; i < SEQT; i++)
            cudaEventCreateWithFlags(&ev[i], cudaEventDisableTiming);
        cudaEventCreateWithFlags(&join, cudaEventDisableTiming);
    }
};
static Aux& aux() { static Aux a; return a; }

// ---------------- launch ------------------------------------------------------
extern "C" void kernel_launch(void* const* d_in, const int* in_sizes, int n_in,
                              void* d_out, int out_size) {
    const float* enc  = (const float*)d_in[0];
    const int*   caps = (const int*  )d_in[1];
    const float* emb  = (const float*)d_in[2];
    const float* Wih  = (const float*)d_in[3];
    const float* Whh  = (const float*)d_in[4];
    const float* bih  = (const float*)d_in[5];
    const float* bhh  = (const float*)d_in[6];
    const float* Wfc  = (const float*)d_in[7];
    const float* bfc  = (const float*)d_in[8];
    float* out = (float*)d_out;

    Aux& ax = aux();

    cudaFuncSetAttribute(ip_gemm, cudaFuncAttributeMaxDynamicSharedMemorySize, SMEMSZ_128);
    cudaFuncSetAttribute(fc_gemm, cudaFuncAttributeMaxDynamicSharedMemorySize, SMEMSZ_128);
    cudaFuncSetAttribute(lstm_mma_step, cudaFuncAttributeMaxDynamicSharedMemorySize, SMEMSZ_REC);

    void* p;
    cudaGetSymbolAddress(&p, g_xf);    __half* xf   = (__half*)p;
    cudaGetSymbolAddress(&p, g_wihf);  __half* wihf = (__half*)p;
    cudaGetSymbolAddress(&p, g_wfcf);  __half* wfcf = (__half*)p;
    cudaGetSymbolAddress(&p, g_hf16);  __half* hf16 = (__half*)p;
    cudaGetSymbolAddress(&p, g_gpre);  float*  gpre = (float*)p;

    gather_f16<<<MALL, 128>>>(enc, caps, emb);
    cvt_all<<<4096, 256>>>(Wih, Whh, Wfc);

    // input projection: G_pre = X @ W_ih^T + b_ih + b_hh   [3072, 4096]
    ip_gemm<<<dim3(G4 / 128, MALL / 128), 256, SMEMSZ_128>>>(
        xf, wihf, bih, bhh, gpre, EMB, G4);

    // recurrence on the capture stream; FC slice t forked onto s2 as soon as
    // h[t] is ready (runs concurrently with steps t+1..23)
    for (int t = 0; t < SEQT; t++) {
        lstm_mma_step<<<256, 256, SMEMSZ_REC>>>(t);
        cudaEventRecord(ax.ev[t], 0);
        cudaStreamWaitEvent(ax.s2, ax.ev[t], 0);
        fc_gemm<<<dim3(VOCP / 128, 1), 256, SMEMSZ_128, ax.s2>>>(
            hf16, wfcf, bfc, out, HID, VOC, t * 128);
    }
    cudaEventRecord(ax.join, ax.s2);
    cudaStreamWaitEvent(0, ax.join, 0);
}

// round 15
// speedup vs baseline: 1.1801x; 1.1801x over previous
#include <cuda_runtime.h>
#include <cuda_bf16.h>
#include <cuda_fp16.h>
#include <math.h>
#include <stdint.h>

constexpr int BATCH = 128, SEQT = 24, EMB = 512, HID = 1024, VOC = 12000;
constexpr int MALL = SEQT * BATCH;     // 3072, row m = t*128 + b
constexpr int G4 = 4 * HID;            // 4096
constexpr int VOCP = 12032;            // VOC padded to 128
constexpr int BK = 32;                 // K chunk
constexpr int LDT = 40;                // padded smem row stride (16-bit elems)
constexpr int STAGES = 3;
constexpr uint32_t SMEMSZ_128 = STAGES * (128 + 128) * LDT * 2;  // 61440 B
constexpr uint32_t SMEMSZ_REC = STAGES * (64 + 32) * LDT * 2;    // 23040 B

// ---------------- device scratch (allocation forbidden) ---------------------
__device__ __half g_xf[(size_t)MALL * EMB];
__device__ __half g_wihf[(size_t)G4 * EMB];
__device__ __half g_whhf[(size_t)G4 * HID];   // gate-interleaved rows
__device__ __half g_wfcf[(size_t)VOCP * HID];
__device__ __half g_hf16[(size_t)MALL * HID];
__device__ float g_gpre[(size_t)MALL * G4];
__device__ float g_cbuf[2 * BATCH * HID];

// ---------------- helpers ----------------------------------------------------
__device__ __forceinline__ uint32_t smem_u32(const void* p) {
    uint32_t a;
    asm("{ .reg .u64 t; cvta.to.shared.u64 t, %1; cvt.u32.u64 %0, t; }" : "=r"(a) : "l"(p));
    return a;
}
__device__ __forceinline__ void cp16(uint32_t d, const void* s) {
    asm volatile("cp.async.cg.shared.global [%0], [%1], 16;" :: "r"(d), "l"(s));
}
__device__ __forceinline__ void cp_commit() { asm volatile("cp.async.commit_group;"); }
template <int N> __device__ __forceinline__ void cp_wait() {
    asm volatile("cp.async.wait_group %0;" :: "n"(N));
}
__device__ __forceinline__ void ldsm4(uint32_t* r, uint32_t a) {
    asm volatile("ldmatrix.sync.aligned.m8n8.x4.shared.b16 {%0,%1,%2,%3}, [%4];"
                 : "=r"(r[0]), "=r"(r[1]), "=r"(r[2]), "=r"(r[3]) : "r"(a));
}
__device__ __forceinline__ void mma16816h(float* d, const uint32_t* a, const uint32_t* b) {
    asm volatile("mma.sync.aligned.m16n8k16.row.col.f32.f16.f16.f32 "
                 "{%0,%1,%2,%3}, {%4,%5,%6,%7}, {%8,%9}, {%0,%1,%2,%3};"
                 : "+f"(d[0]), "+f"(d[1]), "+f"(d[2]), "+f"(d[3])
                 : "r"(a[0]), "r"(a[1]), "r"(a[2]), "r"(a[3]), "r"(b[0]), "r"(b[1]));
}
__device__ __forceinline__ uint2 f16x4(float4 v) {
    __half2 a = __floats2half2_rn(v.x, v.y);
    __half2 b = __floats2half2_rn(v.z, v.w);
    return make_uint2(*reinterpret_cast<uint32_t*>(&a), *reinterpret_cast<uint32_t*>(&b));
}

// ---------------- preprocessing ----------------------------------------------
// Whh interleave: dst row d -> nblk=d>>5, gate=(d>>3)&3, j=d&7 ;
// src row = gate*HID + nblk*8 + j
constexpr int S1 = G4 * EMB / 4;       // 524288
constexpr int S2 = G4 * HID / 4;       // 1048576
constexpr int S3 = VOCP * HID / 4;     // 3080192
__global__ void cvt_ihh(const float* __restrict__ Wih, const float* __restrict__ Whh) {
    constexpr int TOTAL = S1 + S2;
    for (int i = blockIdx.x * blockDim.x + threadIdx.x; i < TOTAL;
         i += gridDim.x * blockDim.x) {
        if (i < S1) {
            reinterpret_cast<uint2*>(g_wihf)[i] =
                f16x4(reinterpret_cast<const float4*>(Wih)[i]);
        } else {
            const int j = i - S1;
            const int d = j >> 8, k4 = j & 255;
            const int src = ((d >> 3) & 3) * HID + (d >> 5) * 8 + (d & 7);
            reinterpret_cast<uint2*>(g_whhf)[j] =
                f16x4(*reinterpret_cast<const float4*>(Whh + (size_t)src * HID + k4 * 4));
        }
    }
}
__global__ void cvt_wfc(const float* __restrict__ Wfc) {
    for (int j = blockIdx.x * blockDim.x + threadIdx.x; j < S3;
         j += gridDim.x * blockDim.x) {
        const int r = j >> 8;
        float4 v = (r < VOC) ? reinterpret_cast<const float4*>(Wfc)[j]
                             : make_float4(0.f, 0.f, 0.f, 0.f);
        reinterpret_cast<uint2*>(g_wfcf)[j] = f16x4(v);
    }
}
__global__ void gather_f16(const float* __restrict__ enc, const int* __restrict__ caps,
                           const float* __restrict__ emb) {
    const int m = blockIdx.x, t = m >> 7, b = m & 127;
    const float* src = (t == 0) ? enc + (size_t)b * EMB
                                : emb + (size_t)caps[b * SEQT + (t - 1)] * EMB;
    const float4 v = reinterpret_cast<const float4*>(src)[threadIdx.x];
    reinterpret_cast<uint2*>(g_xf)[m * (EMB / 4) + threadIdx.x] = f16x4(v);
}

// ---------------- fp16 single-term mainloop ----------------------------------
// acc += A[MTxK] @ B[NTxK]^T. 256 threads, 8 warps.
// MT=128,NT=128: 2Mx4N (wt 64x32, MI=4,NI=4).
// MT=64, NT=32 : 4Mx2N (wt 16x16, MI=1,NI=2).
template <int MT, int NT, int MI, int NI>
__device__ __forceinline__ void gemm_main_h(
    const __half* __restrict__ A, const __half* __restrict__ B,
    int m0, int n0, int K, uint32_t sm, float (&acc)[MI][NI][4]) {
    constexpr int TAe = MT * LDT;
    constexpr int TBe = NT * LDT;
    constexpr int STAGE = TAe + TBe;
    constexpr int TOT = (MT + NT) * 4;

    const int tid = threadIdx.x, warp = tid >> 5, lane = tid & 31;
    const int wm = (MT == 128) ? (warp & 1) * 64 : (warp & 3) * 16;
    const int wn = (MT == 128) ? (warp >> 1) * 32 : (warp >> 2) * 16;
    const int l8 = lane & 7, lt = lane >> 3;
    const int nk = K / BK;

    auto load_stage = [&](int stage, int k0) {
        const uint32_t sbase = sm + stage * STAGE * 2;
#pragma unroll
        for (int idx = tid; idx < TOT; idx += 256) {
            uint32_t dst;
            const __half* src;
            if (idx < MT * 4) {
                const int r = idx >> 2, c = idx & 3;
                dst = sbase + (r * LDT + c * 8) * 2;
                src = A + (size_t)(m0 + r) * K + k0 + c * 8;
            } else {
                const int j = idx - MT * 4, r = j >> 2, c = j & 3;
                dst = sbase + (TAe + r * LDT + c * 8) * 2;
                src = B + (size_t)(n0 + r) * K + k0 + c * 8;
            }
            cp16(dst, src);
        }
        cp_commit();
    };

    load_stage(0, 0);
    load_stage(1, BK);

    for (int kc = 0; kc < nk; kc++) {
        if (kc == nk - 1) cp_wait<0>(); else cp_wait<1>();
        __syncthreads();
        if (kc + STAGES - 1 < nk)
            load_stage((kc + STAGES - 1) % STAGES, (kc + STAGES - 1) * BK);
        const uint32_t sb = sm + (kc % STAGES) * STAGE * 2;
#pragma unroll
        for (int h = 0; h < 2; h++) {
            const int kk = h * 16;
            uint32_t af[MI][4], bf[NI][2];
#pragma unroll
            for (int mi = 0; mi < MI; mi++) {
                const uint32_t ra = sb +
                    ((wm + mi * 16 + l8 + (lt & 1) * 8) * LDT + kk + (lt >> 1) * 8) * 2;
                ldsm4(af[mi], ra);
            }
#pragma unroll
            for (int nj = 0; nj < NI / 2; nj++) {
                const uint32_t rb = sb + TAe * 2 +
                    ((wn + nj * 16 + l8 + (lt >> 1) * 8) * LDT + kk + (lt & 1) * 8) * 2;
                uint32_t t4[4];
                ldsm4(t4, rb);
                bf[nj * 2][0] = t4[0]; bf[nj * 2][1] = t4[1];
                bf[nj * 2 + 1][0] = t4[2]; bf[nj * 2 + 1][1] = t4[3];
            }
#pragma unroll
            for (int mi = 0; mi < MI; mi++)
#pragma unroll
                for (int ni = 0; ni < NI; ni++)
                    mma16816h(acc[mi][ni], af[mi], bf[ni]);
        }
    }
    __syncthreads();
}

// ---------------- input-proj GEMM: C = X @ Wih^T + b_ih + b_hh ---------------
__global__ __launch_bounds__(256, 2)
void ip_gemm(const __half* __restrict__ A, const __half* __restrict__ B,
             const float* __restrict__ b1, const float* __restrict__ b2,
             float* __restrict__ C, int K, int N) {
    extern __shared__ char smraw[];
    float acc[4][4][4];
#pragma unroll
    for (int a = 0; a < 4; a++)
#pragma unroll
        for (int b = 0; b < 4; b++)
#pragma unroll
            for (int c = 0; c < 4; c++) acc[a][b][c] = 0.f;

    const int m0 = blockIdx.y * 128, n0 = blockIdx.x * 128;
    gemm_main_h<128, 128, 4, 4>(A, B, m0, n0, K, smem_u32(smraw), acc);

    const int lane = threadIdx.x & 31, warp = threadIdx.x >> 5;
    const int wm = (warp & 1) * 64, wn = (warp >> 1) * 32;
    const int g = lane >> 2, tg = lane & 3;
#pragma unroll
    for (int mi = 0; mi < 4; mi++)
#pragma unroll
        for (int half = 0; half < 2; half++) {
            const int m = m0 + wm + mi * 16 + g + half * 8;
            const size_t rowBase = (size_t)m * N;
#pragma unroll
            for (int ni = 0; ni < 4; ni++) {
                const int n = n0 + wn + ni * 8 + tg * 2;
                const float2 bb = *reinterpret_cast<const float2*>(b1 + n);
                const float2 b2v = *reinterpret_cast<const float2*>(b2 + n);
                float2 v;
                v.x = acc[mi][ni][half * 2 + 0] + bb.x + b2v.x;
                v.y = acc[mi][ni][half * 2 + 1] + bb.y + b2v.y;
                *reinterpret_cast<float2*>(C + rowBase + n) = v;
            }
        }
}

// ---------------- FC GEMM chunk: 8 timestep row-blocks -----------------------
// C[(b*24+t), n] = sum_k h[m,k] * Wfc[n,k] + b_fc[n], m = mbase + blockIdx.y*128 + ...
__global__ __launch_bounds__(256, 2)
void fc_gemm(const __half* __restrict__ A, const __half* __restrict__ B,
             const float* __restrict__ b1, float* __restrict__ C, int K, int N,
             int mbase) {
    extern __shared__ char smraw[];
    float acc[4][4][4];
#pragma unroll
    for (int a = 0; a < 4; a++)
#pragma unroll
        for (int b = 0; b < 4; b++)
#pragma unroll
            for (int c = 0; c < 4; c++) acc[a][b][c] = 0.f;

    const int m0 = mbase + blockIdx.y * 128, n0 = blockIdx.x * 128;
    gemm_main_h<128, 128, 4, 4>(A, B, m0, n0, K, smem_u32(smraw), acc);

    const int lane = threadIdx.x & 31, warp = threadIdx.x >> 5;
    const int wm = (warp & 1) * 64, wn = (warp >> 1) * 32;
    const int g = lane >> 2, tg = lane & 3;
#pragma unroll
    for (int mi = 0; mi < 4; mi++)
#pragma unroll
        for (int half = 0; half < 2; half++) {
            const int m = m0 + wm + mi * 16 + g + half * 8;
            const size_t rowBase = ((size_t)(m & 127) * SEQT + (size_t)(m >> 7)) * N;
#pragma unroll
            for (int ni = 0; ni < 4; ni++) {
                const int n = n0 + wn + ni * 8 + tg * 2;
                if (n >= N) continue;
                const float2 bb = *reinterpret_cast<const float2*>(b1 + n);
                float2 v;
                v.x = acc[mi][ni][half * 2 + 0] + bb.x;
                v.y = acc[mi][ni][half * 2 + 1] + bb.y;
                *reinterpret_cast<float2*>(C + rowBase + n) = v;
            }
        }
}

// ---------------- recurrent step: 256 CTAs, tile [64 x 32], fused cell -------
// CTA: nblk = blockIdx>>1 owns hidden [nblk*8, nblk*8+8) x 4 gates (D col
// c = gate*8 + j); mh = blockIdx&1 owns batch rows [mh*64, mh*64+64).
__global__ __launch_bounds__(256, 2)
void lstm_mma_step(int t) {
    extern __shared__ char smraw[];
    const int tid = threadIdx.x;
    const int nblk = blockIdx.x >> 1;
    const int mh = blockIdx.x & 1;
    float* Cs = reinterpret_cast<float*>(smraw);   // [64][36], reuses GEMM smem

    if (t > 0) {
        float acc[1][2][4] = {};
        gemm_main_h<64, 32, 1, 2>(
            g_hf16 + (size_t)(t - 1) * BATCH * HID + (size_t)mh * 64 * HID,
            g_whhf, 0, nblk * 32, HID, smem_u32(smraw), acc);
        const int lane = tid & 31, warp = tid >> 5;
        const int wm = (warp & 3) * 16, wn = (warp >> 2) * 16;
        const int g = lane >> 2, tg = lane & 3;
#pragma unroll
        for (int half = 0; half < 2; half++) {
            const int r = wm + g + half * 8;
#pragma unroll
            for (int ni = 0; ni < 2; ni++) {
                const int c = wn + ni * 8 + tg * 2;
                float2 v;
                v.x = acc[0][ni][half * 2 + 0];
                v.y = acc[0][ni][half * 2 + 1];
                *reinterpret_cast<float2*>(&Cs[r * 36 + c]) = v;
            }
        }
        __syncthreads();
    }

    // cell update: 4 threads per batch row, 2 hidden units each
    const int bl = tid >> 2;              // local row 0..63
    const int b = mh * 64 + bl;
    const int u0 = (tid & 3) * 2;         // unit offset 0,2,4,6
    const int j0 = nblk * 8;
    const float* gp   = g_gpre + ((size_t)t * BATCH + b) * G4;
    const float* cold = g_cbuf + (size_t)(t & 1) * BATCH * HID + (size_t)b * HID;
    float*       cnew = g_cbuf + (size_t)((t + 1) & 1) * BATCH * HID + (size_t)b * HID;
    __half*      hf   = g_hf16 + ((size_t)t * BATCH + b) * HID;

    const float2 pi = *reinterpret_cast<const float2*>(gp + 0 * HID + j0 + u0);
    const float2 pf = *reinterpret_cast<const float2*>(gp + 1 * HID + j0 + u0);
    const float2 pg = *reinterpret_cast<const float2*>(gp + 2 * HID + j0 + u0);
    const float2 po = *reinterpret_cast<const float2*>(gp + 3 * HID + j0 + u0);
    float2 co = make_float2(0.f, 0.f);
    if (t > 0) co = *reinterpret_cast<const float2*>(cold + j0 + u0);

    float cn[2], hn[2];
#pragma unroll
    for (int q = 0; q < 2; q++) {
        float ai = 0.f, af = 0.f, ag = 0.f, ao = 0.f;
        if (t > 0) {
            ai = Cs[bl * 36 + 0  + u0 + q];
            af = Cs[bl * 36 + 8  + u0 + q];
            ag = Cs[bl * 36 + 16 + u0 + q];
            ao = Cs[bl * 36 + 24 + u0 + q];
        }
        const float* pip = &pi.x; const float* pfp = &pf.x;
        const float* pgp = &pg.x; const float* pop = &po.x;
        const float* cop = &co.x;
        const float gi = 1.f / (1.f + expf(-(ai + pip[q])));
        const float gf = 1.f / (1.f + expf(-(af + pfp[q])));
        const float gg = tanhf(ag + pgp[q]);
        const float go = 1.f / (1.f + expf(-(ao + pop[q])));
        const float cv = gf * cop[q] + gi * gg;
        cn[q] = cv;
        hn[q] = go * tanhf(cv);
    }
    *reinterpret_cast<float2*>(cnew + j0 + u0) = make_float2(cn[0], cn[1]);
    __half2 hp = __floats2half2_rn(hn[0], hn[1]);
    *reinterpret_cast<uint32_t*>(hf + j0 + u0) = *reinterpret_cast<uint32_t*>(&hp);
}

// ---------------- stream/event aux (created once, outside capture) -----------
struct Aux {
    cudaStream_t s2;
    cudaEvent_t ev[3];
    cudaEvent_t join;
    Aux() {
        cudaStreamCreateWithFlags(&s2, cudaStreamNonBlocking);
        for (int i = 0; i < 3; i++)
            cudaEventCreateWithFlags(&ev[i], cudaEventDisableTiming);
        cudaEventCreateWithFlags(&join, cudaEventDisableTiming);
    }
};
static Aux& aux() { static Aux a; return a; }

// ---------------- launch ------------------------------------------------------
extern "C" void kernel_launch(void* const* d_in, const int* in_sizes, int n_in,
                              void* d_out, int out_size) {
    const float* enc  = (const float*)d_in[0];
    const int*   caps = (const int*  )d_in[1];
    const float* emb  = (const float*)d_in[2];
    const float* Wih  = (const float*)d_in[3];
    const float* Whh  = (const float*)d_in[4];
    const float* bih  = (const float*)d_in[5];
    const float* bhh  = (const float*)d_in[6];
    const float* Wfc  = (const float*)d_in[7];
    const float* bfc  = (const float*)d_in[8];
    float* out = (float*)d_out;

    Aux& ax = aux();

    cudaFuncSetAttribute(ip_gemm, cudaFuncAttributeMaxDynamicSharedMemorySize, SMEMSZ_128);
    cudaFuncSetAttribute(fc_gemm, cudaFuncAttributeMaxDynamicSharedMemorySize, SMEMSZ_128);
    cudaFuncSetAttribute(lstm_mma_step, cudaFuncAttributeMaxDynamicSharedMemorySize, SMEMSZ_REC);

    void* p;
    cudaGetSymbolAddress(&p, g_xf);    __half* xf   = (__half*)p;
    cudaGetSymbolAddress(&p, g_wihf);  __half* wihf = (__half*)p;
    cudaGetSymbolAddress(&p, g_wfcf);  __half* wfcf = (__half*)p;
    cudaGetSymbolAddress(&p, g_hf16);  __half* hf16 = (__half*)p;
    cudaGetSymbolAddress(&p, g_gpre);  float*  gpre = (float*)p;

    // s2: Wfc conversion overlaps gather/cvt/ip on the main stream
    cvt_wfc<<<2048, 256, 0, ax.s2>>>(Wfc);

    gather_f16<<<MALL, 128>>>(enc, caps, emb);
    cvt_ihh<<<2048, 256>>>(Wih, Whh);

    // input projection: G_pre = X @ W_ih^T + b_ih + b_hh   [3072, 4096]
    ip_gemm<<<dim3(G4 / 128, MALL / 128), 256, SMEMSZ_128>>>(
        xf, wihf, bih, bhh, gpre, EMB, G4);

    // recurrence; after steps 7/15/23 fork an 8-timestep FC chunk onto s2
    for (int t = 0; t < SEQT; t++) {
        lstm_mma_step<<<256, 256, SMEMSZ_REC>>>(t);
        if ((t & 7) == 7) {
            const int chunk = t >> 3;
            cudaEventRecord(ax.ev[chunk], 0);
            cudaStreamWaitEvent(ax.s2, ax.ev[chunk], 0);
            fc_gemm<<<dim3(VOCP / 128, 8), 256, SMEMSZ_128, ax.s2>>>(
                hf16, wfcf, bfc, out, HID, VOC, chunk * 1024);
        }
    }
    cudaEventRecord(ax.join, ax.s2);
    cudaStreamWaitEvent(0, ax.join, 0);
}

// round 16
// speedup vs baseline: 1.2921x; 1.0949x over previous
#include <cuda_runtime.h>
#include <cuda_bf16.h>
#include <cuda_fp16.h>
#include <math.h>
#include <stdint.h>

constexpr int BATCH = 128, SEQT = 24, EMB = 512, HID = 1024, VOC = 12000;
constexpr int MALL = SEQT * BATCH;     // 3072, row m = t*128 + b
constexpr int G4 = 4 * HID;            // 4096
constexpr int VOCP = 12032;            // VOC padded to 128
constexpr int BK = 64;                 // K chunk (was 32)
constexpr int LDT = 72;                // padded smem row stride (16-bit elems)
constexpr int STAGES = 3;
constexpr uint32_t SMEMSZ_128 = STAGES * (128 + 128) * LDT * 2;  // 110592 B
constexpr uint32_t SMEMSZ_REC = STAGES * (64 + 32) * LDT * 2;    // 41472 B

// ---------------- device scratch (allocation forbidden) ---------------------
__device__ __half g_xf[(size_t)MALL * EMB];
__device__ __half g_wihf[(size_t)G4 * EMB];
__device__ __half g_whhf[(size_t)G4 * HID];   // gate-interleaved rows
__device__ __half g_wfcf[(size_t)VOCP * HID];
__device__ __half g_hf16[(size_t)MALL * HID];
__device__ float g_gpre[(size_t)MALL * G4];
__device__ float g_cbuf[2 * BATCH * HID];

// ---------------- helpers ----------------------------------------------------
__device__ __forceinline__ uint32_t smem_u32(const void* p) {
    uint32_t a;
    asm("{ .reg .u64 t; cvta.to.shared.u64 t, %1; cvt.u32.u64 %0, t; }" : "=r"(a) : "l"(p));
    return a;
}
__device__ __forceinline__ void cp16(uint32_t d, const void* s) {
    asm volatile("cp.async.cg.shared.global [%0], [%1], 16;" :: "r"(d), "l"(s));
}
__device__ __forceinline__ void cp_commit() { asm volatile("cp.async.commit_group;"); }
template <int N> __device__ __forceinline__ void cp_wait() {
    asm volatile("cp.async.wait_group %0;" :: "n"(N));
}
__device__ __forceinline__ void ldsm4(uint32_t* r, uint32_t a) {
    asm volatile("ldmatrix.sync.aligned.m8n8.x4.shared.b16 {%0,%1,%2,%3}, [%4];"
                 : "=r"(r[0]), "=r"(r[1]), "=r"(r[2]), "=r"(r[3]) : "r"(a));
}
__device__ __forceinline__ void mma16816h(float* d, const uint32_t* a, const uint32_t* b) {
    asm volatile("mma.sync.aligned.m16n8k16.row.col.f32.f16.f16.f32 "
                 "{%0,%1,%2,%3}, {%4,%5,%6,%7}, {%8,%9}, {%0,%1,%2,%3};"
                 : "+f"(d[0]), "+f"(d[1]), "+f"(d[2]), "+f"(d[3])
                 : "r"(a[0]), "r"(a[1]), "r"(a[2]), "r"(a[3]), "r"(b[0]), "r"(b[1]));
}
__device__ __forceinline__ uint2 f16x4(float4 v) {
    __half2 a = __floats2half2_rn(v.x, v.y);
    __half2 b = __floats2half2_rn(v.z, v.w);
    return make_uint2(*reinterpret_cast<uint32_t*>(&a), *reinterpret_cast<uint32_t*>(&b));
}

// ---------------- preprocessing ----------------------------------------------
// Merged convert: Wih plain | Whh interleave | Wfc padded.
// Whh interleave: dst row d -> nblk=d>>5, gate=(d>>3)&3, j=d&7 ;
// src row = gate*HID + nblk*8 + j
constexpr int S1 = G4 * EMB / 4;       // 524288
constexpr int S2 = G4 * HID / 4;       // 1048576
constexpr int S3 = VOCP * HID / 4;     // 3080192
__global__ void cvt_all(const float* __restrict__ Wih, const float* __restrict__ Whh,
                        const float* __restrict__ Wfc) {
    constexpr int TOTAL = S1 + S2 + S3;
    for (int i = blockIdx.x * blockDim.x + threadIdx.x; i < TOTAL;
         i += gridDim.x * blockDim.x) {
        if (i < S1) {
            reinterpret_cast<uint2*>(g_wihf)[i] =
                f16x4(reinterpret_cast<const float4*>(Wih)[i]);
        } else if (i < S1 + S2) {
            const int j = i - S1;
            const int d = j >> 8, k4 = j & 255;
            const int src = ((d >> 3) & 3) * HID + (d >> 5) * 8 + (d & 7);
            reinterpret_cast<uint2*>(g_whhf)[j] =
                f16x4(*reinterpret_cast<const float4*>(Whh + (size_t)src * HID + k4 * 4));
        } else {
            const int j = i - S1 - S2;
            const int r = j >> 8;
            float4 v = (r < VOC) ? reinterpret_cast<const float4*>(Wfc)[j]
                                 : make_float4(0.f, 0.f, 0.f, 0.f);
            reinterpret_cast<uint2*>(g_wfcf)[j] = f16x4(v);
        }
    }
}
__global__ void gather_f16(const float* __restrict__ enc, const int* __restrict__ caps,
                           const float* __restrict__ emb) {
    const int m = blockIdx.x, t = m >> 7, b = m & 127;
    const float* src = (t == 0) ? enc + (size_t)b * EMB
                                : emb + (size_t)caps[b * SEQT + (t - 1)] * EMB;
    const float4 v = reinterpret_cast<const float4*>(src)[threadIdx.x];
    reinterpret_cast<uint2*>(g_xf)[m * (EMB / 4) + threadIdx.x] = f16x4(v);
}

// ---------------- fp16 single-term mainloop, BK=64 ----------------------------
// acc += A[MTxK] @ B[NTxK]^T. 256 threads, 8 warps.
// MT=128,NT=128: 2Mx4N (wt 64x32, MI=4,NI=4).
// MT=64, NT=32 : 4Mx2N (wt 16x16, MI=1,NI=2).
template <int MT, int NT, int MI, int NI>
__device__ __forceinline__ void gemm_main_h(
    const __half* __restrict__ A, const __half* __restrict__ B,
    int m0, int n0, int K, uint32_t sm, float (&acc)[MI][NI][4]) {
    constexpr int TAe = MT * LDT;
    constexpr int TBe = NT * LDT;
    constexpr int STAGE = TAe + TBe;
    constexpr int TOT = (MT + NT) * 8;     // 8 x 16B segments per 64-elem row

    const int tid = threadIdx.x, warp = tid >> 5, lane = tid & 31;
    const int wm = (MT == 128) ? (warp & 1) * 64 : (warp & 3) * 16;
    const int wn = (MT == 128) ? (warp >> 1) * 32 : (warp >> 2) * 16;
    const int l8 = lane & 7, lt = lane >> 3;
    const int nk = K / BK;

    auto load_stage = [&](int stage, int k0) {
        const uint32_t sbase = sm + stage * STAGE * 2;
#pragma unroll
        for (int idx = tid; idx < TOT; idx += 256) {
            uint32_t dst;
            const __half* src;
            if (idx < MT * 8) {
                const int r = idx >> 3, c = idx & 7;
                dst = sbase + (r * LDT + c * 8) * 2;
                src = A + (size_t)(m0 + r) * K + k0 + c * 8;
            } else {
                const int j = idx - MT * 8, r = j >> 3, c = j & 7;
                dst = sbase + (TAe + r * LDT + c * 8) * 2;
                src = B + (size_t)(n0 + r) * K + k0 + c * 8;
            }
            cp16(dst, src);
        }
        cp_commit();
    };

    load_stage(0, 0);
    load_stage(1, BK);

    for (int kc = 0; kc < nk; kc++) {
        if (kc == nk - 1) cp_wait<0>(); else cp_wait<1>();
        __syncthreads();
        if (kc + STAGES - 1 < nk)
            load_stage((kc + STAGES - 1) % STAGES, (kc + STAGES - 1) * BK);
        const uint32_t sb = sm + (kc % STAGES) * STAGE * 2;
#pragma unroll
        for (int h = 0; h < 4; h++) {            // 4 x K=16 per 64-chunk
            const int kk = h * 16;
            uint32_t af[MI][4], bf[NI][2];
#pragma unroll
            for (int mi = 0; mi < MI; mi++) {
                const uint32_t ra = sb +
                    ((wm + mi * 16 + l8 + (lt & 1) * 8) * LDT + kk + (lt >> 1) * 8) * 2;
                ldsm4(af[mi], ra);
            }
#pragma unroll
            for (int nj = 0; nj < NI / 2; nj++) {
                const uint32_t rb = sb + TAe * 2 +
                    ((wn + nj * 16 + l8 + (lt >> 1) * 8) * LDT + kk + (lt & 1) * 8) * 2;
                uint32_t t4[4];
                ldsm4(t4, rb);
                bf[nj * 2][0] = t4[0]; bf[nj * 2][1] = t4[1];
                bf[nj * 2 + 1][0] = t4[2]; bf[nj * 2 + 1][1] = t4[3];
            }
#pragma unroll
            for (int mi = 0; mi < MI; mi++)
#pragma unroll
                for (int ni = 0; ni < NI; ni++)
                    mma16816h(acc[mi][ni], af[mi], bf[ni]);
        }
    }
    __syncthreads();
}

// ---------------- input-proj GEMM: C = X @ Wih^T + b_ih + b_hh ---------------
__global__ __launch_bounds__(256, 2)
void ip_gemm(const __half* __restrict__ A, const __half* __restrict__ B,
             const float* __restrict__ b1, const float* __restrict__ b2,
             float* __restrict__ C, int K, int N) {
    extern __shared__ char smraw[];
    float acc[4][4][4];
#pragma unroll
    for (int a = 0; a < 4; a++)
#pragma unroll
        for (int b = 0; b < 4; b++)
#pragma unroll
            for (int c = 0; c < 4; c++) acc[a][b][c] = 0.f;

    const int m0 = blockIdx.y * 128, n0 = blockIdx.x * 128;
    gemm_main_h<128, 128, 4, 4>(A, B, m0, n0, K, smem_u32(smraw), acc);

    const int lane = threadIdx.x & 31, warp = threadIdx.x >> 5;
    const int wm = (warp & 1) * 64, wn = (warp >> 1) * 32;
    const int g = lane >> 2, tg = lane & 3;
#pragma unroll
    for (int mi = 0; mi < 4; mi++)
#pragma unroll
        for (int half = 0; half < 2; half++) {
            const int m = m0 + wm + mi * 16 + g + half * 8;
            const size_t rowBase = (size_t)m * N;
#pragma unroll
            for (int ni = 0; ni < 4; ni++) {
                const int n = n0 + wn + ni * 8 + tg * 2;
                const float2 bb = *reinterpret_cast<const float2*>(b1 + n);
                const float2 b2v = *reinterpret_cast<const float2*>(b2 + n);
                float2 v;
                v.x = acc[mi][ni][half * 2 + 0] + bb.x + b2v.x;
                v.y = acc[mi][ni][half * 2 + 1] + bb.y + b2v.y;
                *reinterpret_cast<float2*>(C + rowBase + n) = v;
            }
        }
}

// ---------------- FC GEMM: logits reorder + bias -----------------------------
// C[(b*24+t), n] = sum_k h[m,k] * Wfc[n,k] + b_fc[n], m = t*128+b
__global__ __launch_bounds__(256, 2)
void fc_gemm(const __half* __restrict__ A, const __half* __restrict__ B,
             const float* __restrict__ b1, float* __restrict__ C, int K, int N) {
    extern __shared__ char smraw[];
    float acc[4][4][4];
#pragma unroll
    for (int a = 0; a < 4; a++)
#pragma unroll
        for (int b = 0; b < 4; b++)
#pragma unroll
            for (int c = 0; c < 4; c++) acc[a][b][c] = 0.f;

    const int m0 = blockIdx.y * 128, n0 = blockIdx.x * 128;
    gemm_main_h<128, 128, 4, 4>(A, B, m0, n0, K, smem_u32(smraw), acc);

    const int lane = threadIdx.x & 31, warp = threadIdx.x >> 5;
    const int wm = (warp & 1) * 64, wn = (warp >> 1) * 32;
    const int g = lane >> 2, tg = lane & 3;
#pragma unroll
    for (int mi = 0; mi < 4; mi++)
#pragma unroll
        for (int half = 0; half < 2; half++) {
            const int m = m0 + wm + mi * 16 + g + half * 8;
            const size_t rowBase = ((size_t)(m & 127) * SEQT + (size_t)(m >> 7)) * N;
#pragma unroll
            for (int ni = 0; ni < 4; ni++) {
                const int n = n0 + wn + ni * 8 + tg * 2;
                if (n >= N) continue;
                const float2 bb = *reinterpret_cast<const float2*>(b1 + n);
                float2 v;
                v.x = acc[mi][ni][half * 2 + 0] + bb.x;
                v.y = acc[mi][ni][half * 2 + 1] + bb.y;
                *reinterpret_cast<float2*>(C + rowBase + n) = v;
            }
        }
}

// ---------------- recurrent step: 256 CTAs, tile [64 x 32], fused cell -------
// CTA: nblk = blockIdx>>1 owns hidden [nblk*8, nblk*8+8) x 4 gates (D col
// c = gate*8 + j); mh = blockIdx&1 owns batch rows [mh*64, mh*64+64).
__global__ __launch_bounds__(256, 2)
void lstm_mma_step(int t) {
    extern __shared__ char smraw[];
    const int tid = threadIdx.x;
    const int nblk = blockIdx.x >> 1;
    const int mh = blockIdx.x & 1;
    float* Cs = reinterpret_cast<float*>(smraw);   // [64][36], reuses GEMM smem

    if (t > 0) {
        float acc[1][2][4] = {};
        gemm_main_h<64, 32, 1, 2>(
            g_hf16 + (size_t)(t - 1) * BATCH * HID + (size_t)mh * 64 * HID,
            g_whhf, 0, nblk * 32, HID, smem_u32(smraw), acc);
        const int lane = tid & 31, warp = tid >> 5;
        const int wm = (warp & 3) * 16, wn = (warp >> 2) * 16;
        const int g = lane >> 2, tg = lane & 3;
#pragma unroll
        for (int half = 0; half < 2; half++) {
            const int r = wm + g + half * 8;
#pragma unroll
            for (int ni = 0; ni < 2; ni++) {
                const int c = wn + ni * 8 + tg * 2;
                float2 v;
                v.x = acc[0][ni][half * 2 + 0];
                v.y = acc[0][ni][half * 2 + 1];
                *reinterpret_cast<float2*>(&Cs[r * 36 + c]) = v;
            }
        }
        __syncthreads();
    }

    // cell update: 4 threads per batch row, 2 hidden units each
    const int bl = tid >> 2;              // local row 0..63
    const int b = mh * 64 + bl;
    const int u0 = (tid & 3) * 2;         // unit offset 0,2,4,6
    const int j0 = nblk * 8;
    const float* gp   = g_gpre + ((size_t)t * BATCH + b) * G4;
    const float* cold = g_cbuf + (size_t)(t & 1) * BATCH * HID + (size_t)b * HID;
    float*       cnew = g_cbuf + (size_t)((t + 1) & 1) * BATCH * HID + (size_t)b * HID;
    __half*      hf   = g_hf16 + ((size_t)t * BATCH + b) * HID;

    const float2 pi = *reinterpret_cast<const float2*>(gp + 0 * HID + j0 + u0);
    const float2 pf = *reinterpret_cast<const float2*>(gp + 1 * HID + j0 + u0);
    const float2 pg = *reinterpret_cast<const float2*>(gp + 2 * HID + j0 + u0);
    const float2 po = *reinterpret_cast<const float2*>(gp + 3 * HID + j0 + u0);
    float2 co = make_float2(0.f, 0.f);
    if (t > 0) co = *reinterpret_cast<const float2*>(cold + j0 + u0);

    float cn[2], hn[2];
#pragma unroll
    for (int q = 0; q < 2; q++) {
        float ai = 0.f, af = 0.f, ag = 0.f, ao = 0.f;
        if (t > 0) {
            ai = Cs[bl * 36 + 0  + u0 + q];
            af = Cs[bl * 36 + 8  + u0 + q];
            ag = Cs[bl * 36 + 16 + u0 + q];
            ao = Cs[bl * 36 + 24 + u0 + q];
        }
        const float* pip = &pi.x; const float* pfp = &pf.x;
        const float* pgp = &pg.x; const float* pop = &po.x;
        const float* cop = &co.x;
        const float gi = 1.f / (1.f + expf(-(ai + pip[q])));
        const float gf = 1.f / (1.f + expf(-(af + pfp[q])));
        const float gg = tanhf(ag + pgp[q]);
        const float go = 1.f / (1.f + expf(-(ao + pop[q])));
        const float cv = gf * cop[q] + gi * gg;
        cn[q] = cv;
        hn[q] = go * tanhf(cv);
    }
    *reinterpret_cast<float2*>(cnew + j0 + u0) = make_float2(cn[0], cn[1]);
    __half2 hp = __floats2half2_rn(hn[0], hn[1]);
    *reinterpret_cast<uint32_t*>(hf + j0 + u0) = *reinterpret_cast<uint32_t*>(&hp);
}

// ---------------- launch ------------------------------------------------------
extern "C" void kernel_launch(void* const* d_in, const int* in_sizes, int n_in,
                              void* d_out, int out_size) {
    const float* enc  = (const float*)d_in[0];
    const int*   caps = (const int*  )d_in[1];
    const float* emb  = (const float*)d_in[2];
    const float* Wih  = (const float*)d_in[3];
    const float* Whh  = (const float*)d_in[4];
    const float* bih  = (const float*)d_in[5];
    const float* bhh  = (const float*)d_in[6];
    const float* Wfc  = (const float*)d_in[7];
    const float* bfc  = (const float*)d_in[8];
    float* out = (float*)d_out;

    cudaFuncSetAttribute(ip_gemm, cudaFuncAttributeMaxDynamicSharedMemorySize, SMEMSZ_128);
    cudaFuncSetAttribute(fc_gemm, cudaFuncAttributeMaxDynamicSharedMemorySize, SMEMSZ_128);
    cudaFuncSetAttribute(lstm_mma_step, cudaFuncAttributeMaxDynamicSharedMemorySize, SMEMSZ_REC);

    void* p;
    cudaGetSymbolAddress(&p, g_xf);    __half* xf   = (__half*)p;
    cudaGetSymbolAddress(&p, g_wihf);  __half* wihf = (__half*)p;
    cudaGetSymbolAddress(&p, g_wfcf);  __half* wfcf = (__half*)p;
    cudaGetSymbolAddress(&p, g_hf16);  __half* hf16 = (__half*)p;
    cudaGetSymbolAddress(&p, g_gpre);  float*  gpre = (float*)p;

    gather_f16<<<MALL, 128>>>(enc, caps, emb);
    cvt_all<<<4096, 256>>>(Wih, Whh, Wfc);

    // input projection: G_pre = X @ W_ih^T + b_ih + b_hh   [3072, 4096]
    ip_gemm<<<dim3(G4 / 128, MALL / 128), 256, SMEMSZ_128>>>(
        xf, wihf, bih, bhh, gpre, EMB, G4);

    for (int t = 0; t < SEQT; t++)
        lstm_mma_step<<<256, 256, SMEMSZ_REC>>>(t);

    // FC: logits[b,t,:] = h @ W_fc^T + b_fc   (N padded to 12032, guarded)
    fc_gemm<<<dim3(VOCP / 128, MALL / 128), 256, SMEMSZ_128>>>(
        hf16, wfcf, bfc, out, HID, VOC);
}